// round 14
// baseline (speedup 1.0000x reference)
#include <cuda_runtime.h>
#include <cstdint>

// minGRU bidirectional scan. R14 = R13 pipeline with scan cost amortized:
// 2 chunks of 4096 elems, each thread owns 8 CONTIGUOUS elements (one chain)
// -> warp/block scan ops per element halve. Accepts 2-way LDS conflicts.
// x: [B, 512, L] fp32 -> out: [B, 256, L] fp32.
//   out channel c2 (0..255): rev = c2>=128; h row = x[b,(rev?256:0)+(c2&127),:],
//   gate row = +128 channels. Recurrence (logical order; rev scans t=L-1..0):
//   out_t = a_t*out_{t-1} + b_t,  a = 1/(1+e^gate), b = (1-a)*g(h),
//   g(v) = v>=0 ? 1+v : e^v.

constexpr int L  = 8192;
constexpr int NT = 512;
constexpr int NW = NT / 32;    // 16 warps
constexpr int CE = 4096;       // elements per chunk
constexpr int CB = CE * 4;     // bytes per chunk row = 16 KB

constexpr int SMEM_BYTES = 2 * L * 4 + 2 * 8;   // hbuf | gbuf | mbar[2]

__device__ __forceinline__ float fast_rcp(float v) {
    float r;
    asm("rcp.approx.f32 %0, %1;" : "=f"(r) : "f"(v));
    return r;
}

__device__ __forceinline__ void mbar_wait_p0(uint32_t mbar) {
    uint32_t done;
    asm volatile(
        "{\n\t.reg .pred p;\n\t"
        "mbarrier.try_wait.parity.shared::cta.b64 p, [%1], 0;\n\t"
        "selp.b32 %0, 1, 0, p;\n\t}"
        : "=r"(done) : "r"(mbar) : "memory");
    while (!done) {
        asm volatile(
            "{\n\t.reg .pred p;\n\t"
            "mbarrier.try_wait.parity.shared::cta.b64 p, [%1], 0, 0x989680;\n\t"
            "selp.b32 %0, 1, 0, p;\n\t}"
            : "=r"(done) : "r"(mbar) : "memory");
    }
}

__global__ __launch_bounds__(NT, 3)
void mingru_bidir_kernel(const float* __restrict__ x, float* __restrict__ out) {
    extern __shared__ float smem[];
    float* hbuf = smem;
    float* gbuf = smem + L;
    uint64_t* mbar64 = (uint64_t*)(smem + 2 * L);

    __shared__ float sA[2][NW], sB[2][NW];   // per-chunk warp totals

    const int blk = blockIdx.x;
    const int b   = blk >> 8;
    const int c2  = blk & 255;
    const bool rev = (c2 & 128) != 0;
    const int hch = ((c2 & 128) ? 256 : 0) + (c2 & 127);

    const float* hrow = x + (size_t)(b * 512 + hch) * L;
    const float* grow = hrow + (size_t)128 * L;
    float4* __restrict__ o4 = (float4*)(out + (size_t)(b * 256 + c2) * L);

    const int tid  = threadIdx.x;
    const int lane = tid & 31;
    const int warp = tid >> 5;

    const uint32_t mbar_u32 = (uint32_t)__cvta_generic_to_shared(mbar64);
    const uint32_t hbuf_u32 = (uint32_t)__cvta_generic_to_shared(hbuf);
    const uint32_t gbuf_u32 = (uint32_t)__cvta_generic_to_shared(gbuf);

    // ---- issue 2 chunk loads, first-needed physical chunk first ----
    if (tid == 0) {
        #pragma unroll
        for (int i = 0; i < 2; ++i) {
            const int p = rev ? (1 - i) : i;
            asm volatile("mbarrier.init.shared.b64 [%0], 1;"
                         :: "r"(mbar_u32 + 8 * p) : "memory");
            asm volatile("mbarrier.arrive.expect_tx.shared.b64 _, [%0], %1;"
                         :: "r"(mbar_u32 + 8 * p), "r"(2 * CB) : "memory");
            asm volatile("cp.async.bulk.shared::cta.global.mbarrier::complete_tx::bytes "
                         "[%0], [%1], %2, [%3];"
                         :: "r"(hbuf_u32 + p * CB), "l"(hrow + p * CE),
                            "r"(CB), "r"(mbar_u32 + 8 * p) : "memory");
            asm volatile("cp.async.bulk.shared::cta.global.mbarrier::complete_tx::bytes "
                         "[%0], [%1], %2, [%3];"
                         :: "r"(gbuf_u32 + p * CB), "l"(grow + p * CE),
                            "r"(CB), "r"(mbar_u32 + 8 * p) : "memory");
        }
    }
    __syncthreads();   // mbarrier inits visible before any try_wait

    const float4* h4 = (const float4*)hbuf;
    const float4* g4 = (const float4*)gbuf;

    float carry = 0.0f;   // sequence state entering current chunk

    #pragma unroll
    for (int c = 0; c < 2; ++c) {
        const int p = rev ? (1 - c) : c;          // physical chunk

        mbar_wait_p0(mbar_u32 + 8 * p);

        // logical float4 pair f0, f0+1 -> physical indices
        const int f0 = c * 1024 + 2 * tid;
        const int i0 = rev ? (L / 4 - 1 - f0) : f0;
        const int i1 = rev ? (L / 4 - 2 - f0) : (f0 + 1);

        float4 ha = h4[i0], hb = h4[i1];
        float4 ga = g4[i0], gb = g4[i1];
        if (rev) {
            ha = make_float4(ha.w, ha.z, ha.y, ha.x);
            hb = make_float4(hb.w, hb.z, hb.y, hb.x);
            ga = make_float4(ga.w, ga.z, ga.y, ga.x);
            gb = make_float4(gb.w, gb.z, gb.y, gb.x);
        }
        const float hv[8] = {ha.x, ha.y, ha.z, ha.w, hb.x, hb.y, hb.z, hb.w};
        const float gv[8] = {ga.x, ga.y, ga.z, ga.w, gb.x, gb.y, gb.z, gb.w};

        // ---- pointwise + thread compose (8 elems, one chain) ----
        float av[8], bv[8];
        float A = 1.0f, B = 0.0f;
        #pragma unroll
        for (int k = 0; k < 8; ++k) {
            const float a  = fast_rcp(1.0f + __expf(gv[k]));
            const float gh = (hv[k] >= 0.0f) ? (1.0f + hv[k]) : __expf(hv[k]);
            const float bb = (1.0f - a) * gh;
            av[k] = a;
            bv[k] = bb;
            B = fmaf(B, a, bb);
            A *= a;
        }

        // ---- warp inclusive scan (single chain) ----
        #pragma unroll
        for (int off = 1; off < 32; off <<= 1) {
            const float Au = __shfl_up_sync(0xFFFFFFFFu, A, off);
            const float Bu = __shfl_up_sync(0xFFFFFFFFu, B, off);
            if (lane >= off) {
                B = fmaf(Bu, A, B);
                A *= Au;
            }
        }
        float Ae = __shfl_up_sync(0xFFFFFFFFu, A, 1);
        float Be = __shfl_up_sync(0xFFFFFFFFu, B, 1);
        if (lane == 0) { Ae = 1.0f; Be = 0.0f; }

        if (lane == 31) { sA[c][warp] = A; sB[c][warp] = B; }
        __syncthreads();   // single barrier per chunk (buffers indexed by c)

        // ---- redundant block scan: every warp scans the 16 warp totals ----
        float wa = sA[c][lane & (NW - 1)];
        float wb = sB[c][lane & (NW - 1)];
        #pragma unroll
        for (int off = 1; off < NW; off <<= 1) {
            const float Au = __shfl_up_sync(0xFFFFFFFFu, wa, off);
            const float Bu = __shfl_up_sync(0xFFFFFFFFu, wb, off);
            if (lane >= off) {
                wb = fmaf(Bu, wa, wb);
                wa *= Au;
            }
        }
        const int src = (warp == 0) ? 0 : (warp - 1);
        float prevA = __shfl_sync(0xFFFFFFFFu, wa, src);
        float prevB = __shfl_sync(0xFFFFFFFFu, wb, src);
        if (warp == 0) { prevA = 1.0f; prevB = 0.0f; }
        const float totA = __shfl_sync(0xFFFFFFFFu, wa, NW - 1);
        const float totB = __shfl_sync(0xFFFFFFFFu, wb, NW - 1);

        // ---- replay (8 elems) + 2 coalesced STG.128 ----
        float s = fmaf(Ae, fmaf(prevA, carry, prevB), Be);
        float o[8];
        #pragma unroll
        for (int k = 0; k < 8; ++k) {
            s = fmaf(av[k], s, bv[k]);
            o[k] = s;
        }
        if (!rev) {
            o4[i0] = make_float4(o[0], o[1], o[2], o[3]);
            o4[i1] = make_float4(o[4], o[5], o[6], o[7]);
        } else {
            o4[i0] = make_float4(o[3], o[2], o[1], o[0]);
            o4[i1] = make_float4(o[7], o[6], o[5], o[4]);
        }

        carry = fmaf(totA, carry, totB);   // state entering next chunk
    }
}

extern "C" void kernel_launch(void* const* d_in, const int* in_sizes, int n_in,
                              void* d_out, int out_size) {
    const float* x = (const float*)d_in[0];
    float* out = (float*)d_out;
    const int B = in_sizes[0] / (512 * L);
    cudaFuncSetAttribute(mingru_bidir_kernel,
                         cudaFuncAttributeMaxDynamicSharedMemorySize, SMEM_BYTES);
    mingru_bidir_kernel<<<B * 256, NT, SMEM_BYTES>>>(x, out);
}

// round 15
// speedup vs baseline: 1.0608x; 1.0608x over previous
#include <cuda_runtime.h>
#include <cstdint>

// minGRU bidirectional scan. R15: NT=256, 4 chunks of 2048 (EPT=8 contiguous),
// 2-stage smem ring refilled by TMA inside the chunk loop -> 33KB/CTA,
// 6 CTAs/SM. Keeps R13's 4 spread store points + R14's amortized scan.
// x: [B, 512, L] fp32 -> out: [B, 256, L] fp32.
//   out channel c2 (0..255): rev = c2>=128; h row = x[b,(rev?256:0)+(c2&127),:],
//   gate row = +128 channels. Recurrence (logical order; rev scans t=L-1..0):
//   out_t = a_t*out_{t-1} + b_t,  a = 1/(1+e^gate), b = (1-a)*g(h),
//   g(v) = v>=0 ? 1+v : e^v.

constexpr int L  = 8192;
constexpr int NT = 256;
constexpr int NW = NT / 32;    // 8 warps
constexpr int CE = 2048;       // elements per chunk
constexpr int CF = CE / 4;     // float4s per chunk = 512
constexpr int CB = CE * 4;     // bytes per chunk row = 8 KB

// smem: stage s (s=0,1): h-chunk[CB] | g-chunk[CB]; then mbar[2]
constexpr int SMEM_BYTES = 2 * 2 * CB + 2 * 8;

__device__ __forceinline__ float fast_rcp(float v) {
    float r;
    asm("rcp.approx.f32 %0, %1;" : "=f"(r) : "f"(v));
    return r;
}

__device__ __forceinline__ void mbar_wait(uint32_t mbar, uint32_t parity) {
    uint32_t done;
    asm volatile(
        "{\n\t.reg .pred p;\n\t"
        "mbarrier.try_wait.parity.shared::cta.b64 p, [%1], %2;\n\t"
        "selp.b32 %0, 1, 0, p;\n\t}"
        : "=r"(done) : "r"(mbar), "r"(parity) : "memory");
    while (!done) {
        asm volatile(
            "{\n\t.reg .pred p;\n\t"
            "mbarrier.try_wait.parity.shared::cta.b64 p, [%1], %2, 0x989680;\n\t"
            "selp.b32 %0, 1, 0, p;\n\t}"
            : "=r"(done) : "r"(mbar), "r"(parity) : "memory");
    }
}

__device__ __forceinline__ void load_chunk(const float* hsrc, const float* gsrc,
                                           uint32_t hdst, uint32_t gdst,
                                           uint32_t mbar) {
    asm volatile("mbarrier.arrive.expect_tx.shared.b64 _, [%0], %1;"
                 :: "r"(mbar), "r"(2 * CB) : "memory");
    asm volatile("cp.async.bulk.shared::cta.global.mbarrier::complete_tx::bytes "
                 "[%0], [%1], %2, [%3];"
                 :: "r"(hdst), "l"(hsrc), "r"(CB), "r"(mbar) : "memory");
    asm volatile("cp.async.bulk.shared::cta.global.mbarrier::complete_tx::bytes "
                 "[%0], [%1], %2, [%3];"
                 :: "r"(gdst), "l"(gsrc), "r"(CB), "r"(mbar) : "memory");
}

__global__ __launch_bounds__(NT, 6)
void mingru_bidir_kernel(const float* __restrict__ x, float* __restrict__ out) {
    extern __shared__ float smem[];
    uint64_t* mbar64 = (uint64_t*)(smem + 4 * CF * 4);   // after 2 stages x (h+g)

    __shared__ float sA[2][NW], sB[2][NW];

    const int blk = blockIdx.x;
    const int b   = blk >> 8;
    const int c2  = blk & 255;
    const bool rev = (c2 & 128) != 0;
    const int hch = ((c2 & 128) ? 256 : 0) + (c2 & 127);

    const float* hrow = x + (size_t)(b * 512 + hch) * L;
    const float* grow = hrow + (size_t)128 * L;
    float4* __restrict__ o4 = (float4*)(out + (size_t)(b * 256 + c2) * L);

    const int tid  = threadIdx.x;
    const int lane = tid & 31;
    const int warp = tid >> 5;

    const uint32_t smem_u32 = (uint32_t)__cvta_generic_to_shared(smem);
    const uint32_t mbar_u32 = (uint32_t)__cvta_generic_to_shared(mbar64);

    // ---- init barriers, load chunks 0 and 1 into stages 0 and 1 ----
    if (tid == 0) {
        #pragma unroll
        for (int s = 0; s < 2; ++s)
            asm volatile("mbarrier.init.shared.b64 [%0], 1;"
                         :: "r"(mbar_u32 + 8 * s) : "memory");
        #pragma unroll
        for (int c = 0; c < 2; ++c) {
            const int p = rev ? (3 - c) : c;       // physical chunk
            load_chunk(hrow + p * CE, grow + p * CE,
                       smem_u32 + (c & 1) * 2 * CB,
                       smem_u32 + (c & 1) * 2 * CB + CB,
                       mbar_u32 + 8 * (c & 1));
        }
    }
    __syncthreads();   // mbarrier inits visible before any try_wait

    float carry = 0.0f;

    #pragma unroll
    for (int c = 0; c < 4; ++c) {
        const int s = c & 1;                       // ring stage
        mbar_wait(mbar_u32 + 8 * s, (uint32_t)((c >> 1) & 1));

        const float4* h4 = (const float4*)(smem + s * 2 * CF * 4);
        const float4* g4 = h4 + CF;

        // thread owns logical f4 pair j0=2t, j1=2t+1 within the chunk
        const int j0 = 2 * tid;
        const int i0 = rev ? (CF - 1 - j0) : j0;
        const int i1 = rev ? (CF - 2 - j0) : (j0 + 1);

        float4 ha = h4[i0], hb = h4[i1];
        float4 ga = g4[i0], gb = g4[i1];
        if (rev) {
            ha = make_float4(ha.w, ha.z, ha.y, ha.x);
            hb = make_float4(hb.w, hb.z, hb.y, hb.x);
            ga = make_float4(ga.w, ga.z, ga.y, ga.x);
            gb = make_float4(gb.w, gb.z, gb.y, gb.x);
        }
        const float hv[8] = {ha.x, ha.y, ha.z, ha.w, hb.x, hb.y, hb.z, hb.w};
        const float gv[8] = {ga.x, ga.y, ga.z, ga.w, gb.x, gb.y, gb.z, gb.w};

        // ---- pointwise + thread compose (8 elems, one chain) ----
        float av[8], bv[8];
        float A = 1.0f, B = 0.0f;
        #pragma unroll
        for (int k = 0; k < 8; ++k) {
            const float a  = fast_rcp(1.0f + __expf(gv[k]));
            const float gh = (hv[k] >= 0.0f) ? (1.0f + hv[k]) : __expf(hv[k]);
            const float bb = (1.0f - a) * gh;
            av[k] = a;
            bv[k] = bb;
            B = fmaf(B, a, bb);
            A *= a;
        }

        // ---- warp inclusive scan ----
        #pragma unroll
        for (int off = 1; off < 32; off <<= 1) {
            const float Au = __shfl_up_sync(0xFFFFFFFFu, A, off);
            const float Bu = __shfl_up_sync(0xFFFFFFFFu, B, off);
            if (lane >= off) {
                B = fmaf(Bu, A, B);
                A *= Au;
            }
        }
        float Ae = __shfl_up_sync(0xFFFFFFFFu, A, 1);
        float Be = __shfl_up_sync(0xFFFFFFFFu, B, 1);
        if (lane == 0) { Ae = 1.0f; Be = 0.0f; }

        if (lane == 31) { sA[s][warp] = A; sB[s][warp] = B; }
        __syncthreads();   // totals visible; stage s fully consumed

        // ---- refill: stage s is free -> TMA chunk c+2 (overlaps the rest) ----
        if (tid == 0 && c + 2 < 4) {
            const int p2 = rev ? (3 - (c + 2)) : (c + 2);
            load_chunk(hrow + p2 * CE, grow + p2 * CE,
                       smem_u32 + s * 2 * CB,
                       smem_u32 + s * 2 * CB + CB,
                       mbar_u32 + 8 * s);
        }

        // ---- redundant block scan: every warp scans the 8 warp totals ----
        float wa = sA[s][lane & (NW - 1)];
        float wb = sB[s][lane & (NW - 1)];
        #pragma unroll
        for (int off = 1; off < NW; off <<= 1) {
            const float Au = __shfl_up_sync(0xFFFFFFFFu, wa, off);
            const float Bu = __shfl_up_sync(0xFFFFFFFFu, wb, off);
            if (lane >= off) {
                wb = fmaf(Bu, wa, wb);
                wa *= Au;
            }
        }
        const int src = (warp == 0) ? 0 : (warp - 1);
        float prevA = __shfl_sync(0xFFFFFFFFu, wa, src);
        float prevB = __shfl_sync(0xFFFFFFFFu, wb, src);
        if (warp == 0) { prevA = 1.0f; prevB = 0.0f; }
        const float totA = __shfl_sync(0xFFFFFFFFu, wa, NW - 1);
        const float totB = __shfl_sync(0xFFFFFFFFu, wb, NW - 1);

        // ---- replay (8 elems) + 2 coalesced STG.128 ----
        float st = fmaf(Ae, fmaf(prevA, carry, prevB), Be);
        float o[8];
        #pragma unroll
        for (int k = 0; k < 8; ++k) {
            st = fmaf(av[k], st, bv[k]);
            o[k] = st;
        }
        // logical f4 in sequence = c*CF + j -> physical global f4
        const int gf0 = c * CF + j0;
        const int go0 = rev ? (L / 4 - 1 - gf0) : gf0;
        const int go1 = rev ? (L / 4 - 2 - gf0) : (gf0 + 1);
        if (!rev) {
            o4[go0] = make_float4(o[0], o[1], o[2], o[3]);
            o4[go1] = make_float4(o[4], o[5], o[6], o[7]);
        } else {
            o4[go0] = make_float4(o[3], o[2], o[1], o[0]);
            o4[go1] = make_float4(o[7], o[6], o[5], o[4]);
        }

        carry = fmaf(totA, carry, totB);
    }
}

extern "C" void kernel_launch(void* const* d_in, const int* in_sizes, int n_in,
                              void* d_out, int out_size) {
    const float* x = (const float*)d_in[0];
    float* out = (float*)d_out;
    const int B = in_sizes[0] / (512 * L);
    cudaFuncSetAttribute(mingru_bidir_kernel,
                         cudaFuncAttributeMaxDynamicSharedMemorySize, SMEM_BYTES);
    mingru_bidir_kernel<<<B * 256, NT, SMEM_BYTES>>>(x, out);
}